// round 13
// baseline (speedup 1.0000x reference)
#include <cuda_runtime.h>
#include <cuda_fp16.h>
#include <cstdint>

// Problem constants
#define BATCH   32
#define NPATCH  576
#define MTOT    (BATCH * NPATCH)   // 18432
#define KDIM    768                // 3*16*16
#define EMBED   768
#define NKT     24                 // k-tiles of 32

// ---------------------------------------------------------------------------
// Scratch, k-major, 64B rows, quad-XOR swizzle:
//   g_A2[t][patch][32]: quad q of row p stored at byte (q ^ ((p>>1)&3))*16
//   g_B2[t][e][32]    : same with e
// A GEMM tile (t, 128 rows) is a CONTIGUOUS 8KB block -> cp.async.bulk.
// ---------------------------------------------------------------------------
__device__ __align__(256) __half g_A2[(size_t)NKT * MTOT * 32];
__device__ __align__(256) __half g_B2[(size_t)NKT * EMBED * 32];

// ---------------------------------------------------------------------------
// Helpers (base sm_103-target-legal: mbarrier + cp.async.bulk are sm_90 base)
// ---------------------------------------------------------------------------
__device__ __forceinline__ uint32_t smem_u32(const void* p) {
    uint32_t a;
    asm("{ .reg .u64 t; cvta.to.shared.u64 t, %1; cvt.u32.u64 %0, t; }" : "=r"(a) : "l"(p));
    return a;
}

#define MBAR_INIT(addr, cnt) \
    asm volatile("mbarrier.init.shared.b64 [%0], %1;" :: "r"(addr), "r"(cnt) : "memory")

#define MBAR_ARRIVE(addr) \
    asm volatile("mbarrier.arrive.shared.b64 _, [%0];" :: "r"(addr) : "memory")

#define MBAR_EXPECT_TX(addr, bytes) \
    asm volatile("mbarrier.arrive.expect_tx.shared.b64 _, [%0], %1;" \
                 :: "r"(addr), "r"(bytes) : "memory")

#define MBAR_WAIT_PARITY(mbar_addr, parity) do {                                        \
    uint32_t _mbar = (uint32_t)(mbar_addr);                                             \
    uint32_t _par  = (uint32_t)(parity);                                                \
    uint32_t _done;                                                                     \
    asm volatile("{\n\t.reg .pred p;\n\t"                                               \
        "mbarrier.try_wait.parity.acquire.cta.shared::cta.b64 p, [%1], %2;\n\t"         \
        "selp.b32 %0, 1, 0, p;\n\t}"                                                    \
        : "=r"(_done) : "r"(_mbar), "r"(_par) : "memory");                              \
    if (!_done) {                                                                       \
        asm volatile("{\n\t.reg .pred P1;\n\t"                                          \
            "WL_%=:\n\t"                                                                \
            "mbarrier.try_wait.parity.acquire.cta.shared::cta.b64 P1, [%0], %1, 0x989680;\n\t" \
            "@P1 bra.uni WD_%=;\n\t"                                                    \
            "bra.uni WL_%=;\n\t"                                                        \
            "WD_%=:\n\t}"                                                               \
            :: "r"(_mbar), "r"(_par) : "memory");                                       \
    }                                                                                   \
} while (0)

#define BULK_G2S(dst, src, bytes, mbar)                                                 \
    asm volatile("cp.async.bulk.shared::cluster.global.mbarrier::complete_tx::bytes "   \
        "[%0], [%1], %2, [%3];"                                                         \
        :: "r"(dst), "l"(src), "r"(bytes), "r"(mbar) : "memory")

#define FENCE_ASYNC() asm volatile("fence.proxy.async.shared::cta;" ::: "memory")

#define LDSM_X4(r, addr)                                                        \
    asm volatile("ldmatrix.sync.aligned.m8n8.x4.shared.b16 {%0,%1,%2,%3}, [%4];" \
        : "=r"((r)[0]), "=r"((r)[1]), "=r"((r)[2]), "=r"((r)[3]) : "r"(addr))

#define MMA_F16(d, a, b0, b1)                                                   \
    asm volatile("mma.sync.aligned.m16n8k16.row.col.f32.f16.f16.f32 "           \
        "{%0,%1,%2,%3}, {%4,%5,%6,%7}, {%8,%9}, {%0,%1,%2,%3};"                 \
        : "+f"((d)[0]), "+f"((d)[1]), "+f"((d)[2]), "+f"((d)[3])                \
        : "r"((a)[0]), "r"((a)[1]), "r"((a)[2]), "r"((a)[3]), "r"(b0), "r"(b1))

// ---------------------------------------------------------------------------
// Kernel 1 (fused): blocks [0,2304): gather -> g_A2 (cooperative row loads)
//                   blocks [2304,2592): proj_w -> g_B2
// Lane map (gather): r = lane>>3 (row-in-group), q = lane&7 (quad).
// One LDG.128 loads 4 image rows x 80B contiguous -> ~8 wavefronts (was 32).
// Warp-uniform shift s resolved with 3 __shfl_down.
// ---------------------------------------------------------------------------
static constexpr int GROW = 32;    // fp16 staging bytes per row-task
static constexpr int GPAT = 1600;  // staging bytes per patch (50 quads; phase-2 conflict-free)

__global__ __launch_bounds__(256) void prep_kernel(const float* __restrict__ x,
                                                   const int* __restrict__ h_idx,
                                                   const int* __restrict__ w_idx,
                                                   const float* __restrict__ pw) {
    if (blockIdx.x >= 2304) {
        // ---- B prep: one thread per 16B quad ----
        int i = (blockIdx.x - 2304) * 256 + threadIdx.x;   // [0, 73728)
        int e  = i / 96;            // col (embed row) 0..767
        int g  = i - e * 96;        // quad-in-row 0..95
        int t = g >> 2, q = g & 3;
        const float4* s = reinterpret_cast<const float4*>(pw + (size_t)e * KDIM + t * 32 + q * 8);
        float4 v0 = s[0], v1 = s[1];
        __half2 h0 = __halves2half2(__float2half_rn(v0.x), __float2half_rn(v0.y));
        __half2 h1 = __halves2half2(__float2half_rn(v0.z), __float2half_rn(v0.w));
        __half2 h2 = __halves2half2(__float2half_rn(v1.x), __float2half_rn(v1.y));
        __half2 h3 = __halves2half2(__float2half_rn(v1.z), __float2half_rn(v1.w));
        __half* dst = g_B2 + ((size_t)t * EMBED + e) * 32 + ((q ^ ((e >> 1) & 3)) << 3);
        *reinterpret_cast<uint4*>(dst) = make_uint4(
            *reinterpret_cast<unsigned*>(&h0), *reinterpret_cast<unsigned*>(&h1),
            *reinterpret_cast<unsigned*>(&h2), *reinterpret_cast<unsigned*>(&h3));
        return;
    }
    __shared__ __align__(16) char stg[8 * GPAT];
    int tid = threadIdx.x;
    int wid = tid >> 5, lane = tid & 31;
    int r = lane >> 3, q = lane & 7;
    int base_p = blockIdx.x << 3;
    int p = base_p + wid;            // this warp's patch
    int b = p / NPATCH;
    int h = h_idx[p];
    int w = w_idx[p];
    int s  = w & 3;
    int a0 = w & ~3;
    const float* xb = x + (size_t)b * (3 * 384 * 384);
    char* wstg = stg + wid * GPAT;
    bool loader = (q < 5);
    bool producer = (q < 4);

    // Phase 1: cooperative gather + shuffle-shift + convert into staging
#pragma unroll
    for (int i = 0; i < 12; i++) {
        int rr = i * 4 + r;                   // row task 0..47 (c*16 + ph)
        int c = rr >> 4, ph = rr & 15;
        float4 v = make_float4(0.f, 0.f, 0.f, 0.f);
        if (loader)
            v = *reinterpret_cast<const float4*>(
                xb + (size_t)(c * 384 + h + ph) * 384 + a0 + q * 4);
        float n0 = __shfl_down_sync(0xffffffffu, v.x, 1);
        float n1 = __shfl_down_sync(0xffffffffu, v.y, 1);
        float n2 = __shfl_down_sync(0xffffffffu, v.z, 1);
        if (producer) {
            float e0, e1, e2, e3;
            switch (s) {                       // warp-uniform
                case 0:  e0 = v.x; e1 = v.y; e2 = v.z; e3 = v.w; break;
                case 1:  e0 = v.y; e1 = v.z; e2 = v.w; e3 = n0;  break;
                case 2:  e0 = v.z; e1 = v.w; e2 = n0;  e3 = n1;  break;
                default: e0 = v.w; e1 = n0;  e2 = n1;  e3 = n2;  break;
            }
            __half2 p0 = __halves2half2(__float2half_rn(e0), __float2half_rn(e1));
            __half2 p1 = __halves2half2(__float2half_rn(e2), __float2half_rn(e3));
            *reinterpret_cast<uint2*>(wstg + rr * GROW + q * 8) =
                make_uint2(*reinterpret_cast<unsigned*>(&p0),
                           *reinterpret_cast<unsigned*>(&p1));
        }
    }
    __syncthreads();

    // Phase 2: coalesced write-out. 768 quads of 16B per block, 3 per thread.
#pragma unroll
    for (int i = 0; i < 3; i++) {
        int j = tid + i * 256;               // 0..767
        int t = j >> 5;                      // k-tile 0..23
        int rem = j & 31;
        int pl = rem >> 2, qq = rem & 3;
        int rr = 2 * t + (qq >> 1);
        const char* src = stg + pl * GPAT + rr * GROW + ((qq & 1) << 4);
        uint4 v = *reinterpret_cast<const uint4*>(src);
        int pg = base_p + pl;
        __half* dst = g_A2 + ((size_t)t * MTOT + pg) * 32 + ((qq ^ ((pg >> 1) & 3)) << 3);
        *reinterpret_cast<uint4*>(dst) = v;
    }
}

// ---------------------------------------------------------------------------
// Kernel 2: GEMM. BM=128, BN=128, BK=32 tiles, 8 warps (4m x 2n), 2 CTAs/SM.
// 6-slot (16KB) cp.async.bulk ring, depth-4 prefetch, FULL/EMPTY mbarriers,
// no __syncthreads in main loop. Producer block moved AFTER the X-MMA burst
// so warp 0's bookkeeping never delays its tensor issues.
// ---------------------------------------------------------------------------
static constexpr int SLOT_BYTES = 16384;     // A 8KB + B 8KB
static constexpr int N_SLOT = 6;
static constexpr int GEMM_SMEM = 128 + N_SLOT * SLOT_BYTES;  // 98432 (2 CTAs/SM)

__device__ __forceinline__ void load_frags(uint32_t (&fa)[2][4], uint32_t (&fb)[4][4],
                                           uint32_t a_base, uint32_t b_base, uint32_t xq) {
    LDSM_X4(fa[0], a_base + xq);
    LDSM_X4(fa[1], a_base + 1024 + xq);
#pragma unroll
    for (int nb = 0; nb < 4; nb++) LDSM_X4(fb[nb], b_base + nb * 1024 + xq);
}

__device__ __forceinline__ void mma_all(float (&acc)[2][8][4],
                                        uint32_t (&fa)[2][4], uint32_t (&fb)[4][4]) {
#pragma unroll
    for (int mf = 0; mf < 2; mf++)
#pragma unroll
        for (int nf = 0; nf < 8; nf++) {
            int nb = nf >> 1, sel = nf & 1;
            MMA_F16(acc[mf][nf], fa[mf], fb[nb][sel], fb[nb][2 + sel]);
        }
}

__global__ __launch_bounds__(256, 2) void gemm_kernel(const float* __restrict__ proj_b,
                                                      float* __restrict__ out) {
    extern __shared__ char smem[];
    uint32_t sb = smem_u32(smem);
    int tid = threadIdx.x;
    int lane = tid & 31, wid = tid >> 5;
    int wm = wid & 3, wn = wid >> 2;
    int nbase = blockIdx.x * 128;      // x fastest: 6 CTAs share one A tile in L2
    int mbase = blockIdx.y * 128;

    const uint32_t FULL0 = sb, EMPTY0 = sb + 48;

    float acc[2][8][4];
#pragma unroll
    for (int a = 0; a < 2; a++)
#pragma unroll
        for (int b = 0; b < 8; b++)
#pragma unroll
            for (int c = 0; c < 4; c++) acc[a][b][c] = 0.f;

    int l15 = lane & 15, kh = lane >> 4;
    int key = (l15 >> 1) & 3;
    uint32_t base = sb + 128;
    uint32_t a_off = base + (uint32_t)((wm * 32 + l15) * 64);          // A at slot+0
    uint32_t b_off = base + 8192 + (uint32_t)((wn * 64 + l15) * 64);   // B at slot+8KB
    uint32_t xqs[2];
#pragma unroll
    for (int ks = 0; ks < 2; ks++) xqs[ks] = (uint32_t)(((ks * 2 + kh) ^ key) << 4);

    const char* srcA = reinterpret_cast<const char*>(g_A2) + (size_t)mbase * 64;
    const char* srcB = reinterpret_cast<const char*>(g_B2) + (size_t)nbase * 64;
    const size_t strideA = (size_t)MTOT * 64;    // bytes per k-tile plane of A
    const size_t strideB = (size_t)EMBED * 64;

    if (tid == 0) {
#pragma unroll
        for (int s = 0; s < N_SLOT; s++) {
            MBAR_INIT(FULL0 + s * 8, 1u);   // tx-based completion
            MBAR_INIT(EMPTY0 + s * 8, 8u);  // one arrive per warp
        }
    }
    __syncthreads();   // only CTA-wide barrier: after init
    if (tid == 0) {
#pragma unroll
        for (int s = 0; s < 4; s++) {       // prefetch tiles 0..3
            MBAR_EXPECT_TX(FULL0 + s * 8, (uint32_t)SLOT_BYTES);
            BULK_G2S(base + s * SLOT_BYTES,        srcA + s * strideA, 8192u, FULL0 + s * 8);
            BULK_G2S(base + s * SLOT_BYTES + 8192, srcB + s * strideB, 8192u, FULL0 + s * 8);
        }
    }

    uint32_t xa[2][4], xb[4][4];   // fragment buffer X (kstep 0)
    uint32_t ya[2][4], yb[4][4];   // fragment buffer Y (kstep 1)

    MBAR_WAIT_PARITY(FULL0, 0);
    load_frags(xa, xb, a_off, b_off, xqs[0]);

#pragma unroll
    for (int t = 0; t < NKT; t++) {
        const int s = t % N_SLOT;
        const uint32_t slot = (uint32_t)(s * SLOT_BYTES);
        // kstep1 frags (last read of slot s by this warp), then release slot.
        load_frags(ya, yb, a_off + slot, b_off + slot, xqs[1]);
        if (lane == 0) MBAR_ARRIVE(EMPTY0 + s * 8);
        mma_all(acc, xa, xb);
        // Producer: refill slot (t+4)%6 with tile t+4 (after X-MMAs issued so
        // warp 0's EMPTY-wait never delays its tensor stream).
        if (t + 4 < NKT && tid == 0) {
            const int T = t + 4, ps = T % N_SLOT, u = T / N_SLOT;
            if (u >= 1) MBAR_WAIT_PARITY(EMPTY0 + ps * 8, (u - 1) & 1);
            FENCE_ASYNC();
            MBAR_EXPECT_TX(FULL0 + ps * 8, (uint32_t)SLOT_BYTES);
            BULK_G2S(base + ps * SLOT_BYTES,        srcA + (size_t)T * strideA, 8192u, FULL0 + ps * 8);
            BULK_G2S(base + ps * SLOT_BYTES + 8192, srcB + (size_t)T * strideB, 8192u, FULL0 + ps * 8);
        }
        if (t < NKT - 1) {
            const int nt = t + 1, ns = nt % N_SLOT;
            MBAR_WAIT_PARITY(FULL0 + ns * 8, (nt / N_SLOT) & 1);
            load_frags(xa, xb, a_off + (uint32_t)(ns * SLOT_BYTES),
                       b_off + (uint32_t)(ns * SLOT_BYTES), xqs[0]);
        }
        mma_all(acc, ya, yb);
    }

    // Epilogue: acc + bias -> out
#pragma unroll
    for (int mf = 0; mf < 2; mf++) {
#pragma unroll
        for (int nf = 0; nf < 8; nf++) {
            int row = mbase + wm * 32 + mf * 16 + (lane >> 2);
            int col = nbase + wn * 64 + nf * 8 + (lane & 3) * 2;
            float2 bv = *reinterpret_cast<const float2*>(proj_b + col);
            float2 o0 = make_float2(acc[mf][nf][0] + bv.x, acc[mf][nf][1] + bv.y);
            float2 o1 = make_float2(acc[mf][nf][2] + bv.x, acc[mf][nf][3] + bv.y);
            *reinterpret_cast<float2*>(out + (size_t)row * EMBED + col) = o0;
            *reinterpret_cast<float2*>(out + (size_t)(row + 8) * EMBED + col) = o1;
        }
    }
}

// ---------------------------------------------------------------------------
// kernel_launch
// ---------------------------------------------------------------------------
extern "C" void kernel_launch(void* const* d_in, const int* in_sizes, int n_in,
                              void* d_out, int out_size) {
    const float* x      = (const float*)d_in[0];
    const int*   h_idx  = (const int*)d_in[1];
    const int*   w_idx  = (const int*)d_in[2];
    const float* proj_w = (const float*)d_in[3];
    const float* proj_b = (const float*)d_in[4];
    float* out = (float*)d_out;

    prep_kernel<<<2592, 256>>>(x, h_idx, w_idx, proj_w);  // gather + B prep fused

    cudaFuncSetAttribute(gemm_kernel, cudaFuncAttributeMaxDynamicSharedMemorySize, GEMM_SMEM);
    gemm_kernel<<<dim3(6, 144), 256, GEMM_SMEM>>>(proj_b, out);
}

// round 14
// speedup vs baseline: 1.0691x; 1.0691x over previous
#include <cuda_runtime.h>
#include <cuda_fp16.h>
#include <cstdint>

// Problem constants
#define BATCH   32
#define NPATCH  576
#define MTOT    (BATCH * NPATCH)   // 18432
#define KDIM    768                // 3*16*16
#define EMBED   768
#define NKT2    12                 // super-k-tiles of 64

// ---------------------------------------------------------------------------
// Scratch, k-major + XOR-swizzled so GEMM tiles are CONTIGUOUS 16KB blocks:
//   g_A2[kt2][patch][64]  (128B per row, quad q stored at q ^ (patch&7))
//   g_B2[kt2][e][64]
// ---------------------------------------------------------------------------
__device__ __align__(256) __half g_A2[(size_t)NKT2 * MTOT * 64];
__device__ __align__(256) __half g_B2[(size_t)NKT2 * EMBED * 64];

// ---------------------------------------------------------------------------
// Helpers (base sm_103-target-legal: mbarrier + cp.async.bulk are sm_90 base)
// ---------------------------------------------------------------------------
__device__ __forceinline__ uint32_t smem_u32(const void* p) {
    uint32_t a;
    asm("{ .reg .u64 t; cvta.to.shared.u64 t, %1; cvt.u32.u64 %0, t; }" : "=r"(a) : "l"(p));
    return a;
}

#define MBAR_INIT(addr, cnt) \
    asm volatile("mbarrier.init.shared.b64 [%0], %1;" :: "r"(addr), "r"(cnt) : "memory")

#define MBAR_ARRIVE(addr) \
    asm volatile("mbarrier.arrive.shared.b64 _, [%0];" :: "r"(addr) : "memory")

#define MBAR_EXPECT_TX(addr, bytes) \
    asm volatile("mbarrier.arrive.expect_tx.shared.b64 _, [%0], %1;" \
                 :: "r"(addr), "r"(bytes) : "memory")

#define MBAR_WAIT_PARITY(mbar_addr, parity) do {                                        \
    uint32_t _mbar = (uint32_t)(mbar_addr);                                             \
    uint32_t _par  = (uint32_t)(parity);                                                \
    uint32_t _done;                                                                     \
    asm volatile("{\n\t.reg .pred p;\n\t"                                               \
        "mbarrier.try_wait.parity.acquire.cta.shared::cta.b64 p, [%1], %2;\n\t"         \
        "selp.b32 %0, 1, 0, p;\n\t}"                                                    \
        : "=r"(_done) : "r"(_mbar), "r"(_par) : "memory");                              \
    if (!_done) {                                                                       \
        asm volatile("{\n\t.reg .pred P1;\n\t"                                          \
            "WL_%=:\n\t"                                                                \
            "mbarrier.try_wait.parity.acquire.cta.shared::cta.b64 P1, [%0], %1, 0x989680;\n\t" \
            "@P1 bra.uni WD_%=;\n\t"                                                    \
            "bra.uni WL_%=;\n\t"                                                        \
            "WD_%=:\n\t}"                                                               \
            :: "r"(_mbar), "r"(_par) : "memory");                                       \
    }                                                                                   \
} while (0)

#define BULK_G2S(dst, src, bytes, mbar)                                                 \
    asm volatile("cp.async.bulk.shared::cluster.global.mbarrier::complete_tx::bytes "   \
        "[%0], [%1], %2, [%3];"                                                         \
        :: "r"(dst), "l"(src), "r"(bytes), "r"(mbar) : "memory")

#define FENCE_ASYNC() asm volatile("fence.proxy.async.shared::cta;" ::: "memory")

#define LDSM_X4(r, addr)                                                        \
    asm volatile("ldmatrix.sync.aligned.m8n8.x4.shared.b16 {%0,%1,%2,%3}, [%4];" \
        : "=r"((r)[0]), "=r"((r)[1]), "=r"((r)[2]), "=r"((r)[3]) : "r"(addr))

#define MMA_F16(d, a, b0, b1)                                                   \
    asm volatile("mma.sync.aligned.m16n8k16.row.col.f32.f16.f16.f32 "           \
        "{%0,%1,%2,%3}, {%4,%5,%6,%7}, {%8,%9}, {%0,%1,%2,%3};"                 \
        : "+f"((d)[0]), "+f"((d)[1]), "+f"((d)[2]), "+f"((d)[3])                \
        : "r"((a)[0]), "r"((a)[1]), "r"((a)[2]), "r"((a)[3]), "r"(b0), "r"(b1))

// ---------------------------------------------------------------------------
// Kernel 1 (fused), 192-thread blocks:
//   blocks [0,4608): gather, ONE THREAD PER ROW-TASK (4 patches x 48 rows).
//     Perfect lane balance (R10 idled 25% of lanes). Per-lane shift s via
//     2 FSELs per output; 5th float4 load unconditional (a0+20 <= 384).
//   blocks [4608,4992): proj_w -> g_B2 (one thread per 16B quad).
// Store addresses/data are bit-identical to R10.
// ---------------------------------------------------------------------------
__global__ __launch_bounds__(192) void prep_kernel(const float* __restrict__ x,
                                                   const int* __restrict__ h_idx,
                                                   const int* __restrict__ w_idx,
                                                   const float* __restrict__ pw) {
    if (blockIdx.x >= 4608) {
        // ---- B prep: one thread per 16B quad; 73728 quads over 384 blocks ----
        int i = (blockIdx.x - 4608) * 192 + threadIdx.x;
        int e  = i / 96;            // embed row 0..767
        int g  = i - e * 96;        // quad-in-row 0..95
        int kt2 = g >> 3, q = g & 7;
        const float4* s = reinterpret_cast<const float4*>(pw + (size_t)e * KDIM + kt2 * 64 + q * 8);
        float4 v0 = s[0], v1 = s[1];
        __half2 h0 = __halves2half2(__float2half_rn(v0.x), __float2half_rn(v0.y));
        __half2 h1 = __halves2half2(__float2half_rn(v0.z), __float2half_rn(v0.w));
        __half2 h2 = __halves2half2(__float2half_rn(v1.x), __float2half_rn(v1.y));
        __half2 h3 = __halves2half2(__float2half_rn(v1.z), __float2half_rn(v1.w));
        __half* dst = g_B2 + ((size_t)kt2 * EMBED + e) * 64 + ((q ^ (e & 7)) << 3);
        *reinterpret_cast<uint4*>(dst) = make_uint4(
            *reinterpret_cast<unsigned*>(&h0), *reinterpret_cast<unsigned*>(&h1),
            *reinterpret_cast<unsigned*>(&h2), *reinterpret_cast<unsigned*>(&h3));
        return;
    }
    // ---- gather: thread = (patch-in-block pl, row-task rr) ----
    int tid = threadIdx.x;
    int pl = tid / 48;               // 0..3
    int rr = tid - pl * 48;          // 0..47  (c*16 + ph)
    int p  = (blockIdx.x << 2) + pl; // global patch 0..18431
    int b = p / NPATCH;
    int h = h_idx[p];
    int w = w_idx[p];
    int s  = w & 3;
    int a0 = w & ~3;
    int c = rr >> 4, ph = rr & 15;

    const float* xb = x + (size_t)b * (3 * 384 * 384);
    const float4* src = reinterpret_cast<const float4*>(
        xb + (size_t)(c * 384 + h + ph) * 384 + a0);
    // 5 unconditional loads: a0 <= 364 so a0+20 <= 384 (row end), always in-bounds.
    float4 f0 = src[0], f1 = src[1], f2 = src[2], f3 = src[3], f4 = src[4];
    float e[20] = {f0.x, f0.y, f0.z, f0.w, f1.x, f1.y, f1.z, f1.w,
                   f2.x, f2.y, f2.z, f2.w, f3.x, f3.y, f3.z, f3.w,
                   f4.x, f4.y, f4.z, f4.w};
    // Per-lane shift: o[j] = e[j + s] via 2 selects (no dynamic indexing).
    bool s1 = (s & 1) != 0, s2 = (s & 2) != 0;
    unsigned uh[8];
#pragma unroll
    for (int k = 0; k < 8; k++) {
        int j0 = 2 * k, j1 = 2 * k + 1;
        float a01 = s1 ? e[j0 + 1] : e[j0];
        float a23 = s1 ? e[j0 + 3] : e[j0 + 2];
        float oa  = s2 ? a23 : a01;
        float b01 = s1 ? e[j1 + 1] : e[j1];
        float b23 = s1 ? e[j1 + 3] : e[j1 + 2];
        float ob  = s2 ? b23 : b01;
        __half2 hp = __halves2half2(__float2half_rn(oa), __float2half_rn(ob));
        uh[k] = *reinterpret_cast<unsigned*>(&hp);
    }
    // Store (identical addressing to R10): kt2 = rr>>2, quads q0, q0+1, XOR p&7.
    int kt2 = rr >> 2, q0 = (rr & 3) * 2, p7 = p & 7;
    __half* dst = g_A2 + ((size_t)kt2 * MTOT + p) * 64;
    *reinterpret_cast<uint4*>(dst + ((q0 ^ p7) << 3)) =
        make_uint4(uh[0], uh[1], uh[2], uh[3]);
    *reinterpret_cast<uint4*>(dst + (((q0 + 1) ^ p7) << 3)) =
        make_uint4(uh[4], uh[5], uh[6], uh[7]);
}

// ---------------------------------------------------------------------------
// Kernel 2: GEMM — R10 verbatim (best measured: 60.4us).
// BM=128, BN=128, BK=64, 8 warps (4m x 2n), 2 CTAs/SM.
// cp.async.bulk staging + FULL/EMPTY mbarrier ring (no __syncthreads in loop).
// ---------------------------------------------------------------------------
static constexpr int SLOT_BYTES = 32768;     // A 16KB + B 16KB
static constexpr int N_SLOT = 3;
static constexpr int GEMM_SMEM = 128 + N_SLOT * SLOT_BYTES;  // 98432 (2 CTAs/SM)

__device__ __forceinline__ void load_frags(uint32_t (&fa)[2][4], uint32_t (&fb)[4][4],
                                           uint32_t a_base, uint32_t b_base, uint32_t xq) {
    LDSM_X4(fa[0], a_base + xq);
    LDSM_X4(fa[1], a_base + 2048 + xq);
#pragma unroll
    for (int nb = 0; nb < 4; nb++) LDSM_X4(fb[nb], b_base + nb * 2048 + xq);
}

__device__ __forceinline__ void mma_all(float (&acc)[2][8][4],
                                        uint32_t (&fa)[2][4], uint32_t (&fb)[4][4]) {
#pragma unroll
    for (int mf = 0; mf < 2; mf++)
#pragma unroll
        for (int nf = 0; nf < 8; nf++) {
            int nb = nf >> 1, sel = nf & 1;
            MMA_F16(acc[mf][nf], fa[mf], fb[nb][sel], fb[nb][2 + sel]);
        }
}

__global__ __launch_bounds__(256, 2) void gemm_kernel(const float* __restrict__ proj_b,
                                                      float* __restrict__ out) {
    extern __shared__ char smem[];
    uint32_t sb = smem_u32(smem);
    int tid = threadIdx.x;
    int lane = tid & 31, wid = tid >> 5;
    int wm = wid & 3, wn = wid >> 2;
    int nbase = blockIdx.x * 128;      // x fastest: 6 CTAs share one A tile in L2
    int mbase = blockIdx.y * 128;

    const uint32_t FULL0 = sb, EMPTY0 = sb + 24;

    float acc[2][8][4];
#pragma unroll
    for (int a = 0; a < 2; a++)
#pragma unroll
        for (int b = 0; b < 8; b++)
#pragma unroll
            for (int c = 0; c < 4; c++) acc[a][b][c] = 0.f;

    int l15 = lane & 15, kh = lane >> 4, l7 = lane & 7;
    uint32_t base = sb + 128;
    uint32_t a_off = base + (uint32_t)((wm * 32 + l15) * 128);          // A at slot+0
    uint32_t b_off = base + 16384 + (uint32_t)((wn * 64 + l15) * 128);  // B at slot+16KB
    uint32_t xq[4];
#pragma unroll
    for (int ks = 0; ks < 4; ks++) xq[ks] = (uint32_t)(((ks * 2 + kh) ^ l7) << 4);

    const char* srcA = reinterpret_cast<const char*>(g_A2) + (size_t)mbase * 128;
    const char* srcB = reinterpret_cast<const char*>(g_B2) + (size_t)nbase * 128;
    const size_t strideA = (size_t)MTOT * 128;
    const size_t strideB = (size_t)EMBED * 128;

    if (tid == 0) {
#pragma unroll
        for (int s = 0; s < N_SLOT; s++) {
            MBAR_INIT(FULL0 + s * 8, 1u);   // tx-based completion
            MBAR_INIT(EMPTY0 + s * 8, 8u);  // one arrive per warp
        }
    }
    __syncthreads();   // only CTA-wide barrier: after init
    if (tid == 0) {
#pragma unroll
        for (int s = 0; s < 2; s++) {       // prefetch tiles 0,1
            MBAR_EXPECT_TX(FULL0 + s * 8, (uint32_t)SLOT_BYTES);
            BULK_G2S(base + s * SLOT_BYTES,         srcA + s * strideA, 16384u, FULL0 + s * 8);
            BULK_G2S(base + s * SLOT_BYTES + 16384, srcB + s * strideB, 16384u, FULL0 + s * 8);
        }
    }

    uint32_t xa[2][4], xb[4][4];   // fragment buffer X
    uint32_t ya[2][4], yb[4][4];   // fragment buffer Y

    MBAR_WAIT_PARITY(FULL0, 0);
    load_frags(xa, xb, a_off, b_off, xq[0]);

#pragma unroll
    for (int kt = 0; kt < NKT2; kt++) {
        const int s = kt % N_SLOT;
        const uint32_t slot = (uint32_t)(s * SLOT_BYTES);
        // Producer: refill slot (kt+2)%3 for tile kt+2 once all warps released it.
        if (kt + 2 < NKT2 && tid == 0) {
            const int t = kt + 2, ps = t % N_SLOT, u = t / N_SLOT;
            if (u >= 1) MBAR_WAIT_PARITY(EMPTY0 + ps * 8, (u - 1) & 1);
            FENCE_ASYNC();
            MBAR_EXPECT_TX(FULL0 + ps * 8, (uint32_t)SLOT_BYTES);
            BULK_G2S(base + ps * SLOT_BYTES,         srcA + (size_t)t * strideA, 16384u, FULL0 + ps * 8);
            BULK_G2S(base + ps * SLOT_BYTES + 16384, srcB + (size_t)t * strideB, 16384u, FULL0 + ps * 8);
        }
        // 4 k16-steps, X/Y alternating; LDSM hidden under 16-MMA bursts.
        load_frags(ya, yb, a_off + slot, b_off + slot, xq[1]);
        mma_all(acc, xa, xb);
        load_frags(xa, xb, a_off + slot, b_off + slot, xq[2]);
        mma_all(acc, ya, yb);
        load_frags(ya, yb, a_off + slot, b_off + slot, xq[3]);   // last read of slot s
        if (lane == 0) MBAR_ARRIVE(EMPTY0 + s * 8);              // release slot s
        mma_all(acc, xa, xb);
        if (kt < NKT2 - 1) {
            const int nt = kt + 1, nsl = nt % N_SLOT;
            MBAR_WAIT_PARITY(FULL0 + nsl * 8, (nt / N_SLOT) & 1);
            load_frags(xa, xb, a_off + (uint32_t)(nsl * SLOT_BYTES),
                       b_off + (uint32_t)(nsl * SLOT_BYTES), xq[0]);
        }
        mma_all(acc, ya, yb);
    }

    // Epilogue: acc + bias -> out
#pragma unroll
    for (int mf = 0; mf < 2; mf++) {
#pragma unroll
        for (int nf = 0; nf < 8; nf++) {
            int row = mbase + wm * 32 + mf * 16 + (lane >> 2);
            int col = nbase + wn * 64 + nf * 8 + (lane & 3) * 2;
            float2 bv = *reinterpret_cast<const float2*>(proj_b + col);
            float2 o0 = make_float2(acc[mf][nf][0] + bv.x, acc[mf][nf][1] + bv.y);
            float2 o1 = make_float2(acc[mf][nf][2] + bv.x, acc[mf][nf][3] + bv.y);
            *reinterpret_cast<float2*>(out + (size_t)row * EMBED + col) = o0;
            *reinterpret_cast<float2*>(out + (size_t)(row + 8) * EMBED + col) = o1;
        }
    }
}

// ---------------------------------------------------------------------------
// kernel_launch
// ---------------------------------------------------------------------------
extern "C" void kernel_launch(void* const* d_in, const int* in_sizes, int n_in,
                              void* d_out, int out_size) {
    const float* x      = (const float*)d_in[0];
    const int*   h_idx  = (const int*)d_in[1];
    const int*   w_idx  = (const int*)d_in[2];
    const float* proj_w = (const float*)d_in[3];
    const float* proj_b = (const float*)d_in[4];
    float* out = (float*)d_out;

    prep_kernel<<<4992, 192>>>(x, h_idx, w_idx, proj_w);  // gather (4608) + B prep (384)

    cudaFuncSetAttribute(gemm_kernel, cudaFuncAttributeMaxDynamicSharedMemorySize, GEMM_SMEM);
    gemm_kernel<<<dim3(6, 144), 256, GEMM_SMEM>>>(proj_b, out);
}